// round 8
// baseline (speedup 1.0000x reference)
#include <cuda_runtime.h>
#include <cstdint>

// Scene splatting via tile-binned GATHER:
// out[c, y+r, x+q] += patches[n, c, r, q]; frame C=5,H=4096,W=4096; N=2000 64x64 patches.
// Each 64x64 output tile gathers its overlapping patches and is written exactly once
// (fuses zeroing + accumulation; no atomics on the output).

static constexpr int C  = 5;
static constexpr int H  = 4096;
static constexpr int W  = 4096;
static constexpr int PH = 64;
static constexpr int PW = 64;
static constexpr int N_SRC = 2000;

static constexpr int TILE    = 64;
static constexpr int TILES_X = W / TILE;   // 64
static constexpr int TILES_Y = H / TILE;   // 64
static constexpr int NTILES  = TILES_X * TILES_Y;  // 4096
static constexpr int MAXP    = 128;        // max patches binned per tile (mean ~2)

// Scratch: device globals (no cudaMalloc allowed).
__device__ int g_cnt[NTILES];
__device__ int g_list[NTILES][MAXP];

// ---------------------------------------------------------------------------
// Kernel 0: reset per-tile counters.
// ---------------------------------------------------------------------------
__global__ void reset_kernel() {
    int i = blockIdx.x * blockDim.x + threadIdx.x;
    if (i < NTILES) g_cnt[i] = 0;
}

// ---------------------------------------------------------------------------
// Kernel 1: bin each patch into the (<=4) tiles it overlaps.
// ---------------------------------------------------------------------------
__global__ void bin_kernel(const int* __restrict__ positions) {
    int n = blockIdx.x * blockDim.x + threadIdx.x;
    if (n >= N_SRC) return;
    const int y = positions[2 * n + 0];
    const int x = positions[2 * n + 1];
    const int ty0 = y >> 6, ty1 = (y + PH - 1) >> 6;
    const int tx0 = x >> 6, tx1 = (x + PW - 1) >> 6;
    for (int ty = ty0; ty <= ty1; ty++) {
        for (int tx = tx0; tx <= tx1; tx++) {
            const int t = ty * TILES_X + tx;
            const int slot = atomicAdd(&g_cnt[t], 1);
            if (slot < MAXP) g_list[t][slot] = n;
        }
    }
}

// ---------------------------------------------------------------------------
// Kernel 2: gather. One CTA per (spatial tile, channel).
// 256 threads; thread (q = tid&63, rg = tid>>6) owns pixels (rg+4k, q), k=0..15,
// accumulated in registers. Patch reads and output writes are 128B-coalesced
// per warp. Writes the tile exactly once (zero-filled where no patch covers).
// ---------------------------------------------------------------------------
__global__ __launch_bounds__(256) void gather_kernel(
    const float* __restrict__ patches,    // [N, C, PH, PW]
    const int*   __restrict__ positions,  // [N, 2] (y, x)
    float* __restrict__ out)              // [C, H, W]
{
    const int tile = blockIdx.x;          // 0 .. 4095
    const int c    = blockIdx.y;          // 0 .. 4
    const int TY   = (tile >> 6) * TILE;
    const int TX   = (tile & 63) * TILE;

    const int tid = threadIdx.x;
    const int q   = tid & 63;             // column within tile
    const int rg  = tid >> 6;             // row-group (0..3)

    float acc[16];
    #pragma unroll
    for (int k = 0; k < 16; k++) acc[k] = 0.0f;

    int cnt = g_cnt[tile];
    if (cnt > MAXP) cnt = MAXP;

    for (int i = 0; i < cnt; i++) {
        const int n = g_list[tile][i];
        const int y = positions[2 * n + 0];
        const int x = positions[2 * n + 1];

        const int pq = TX + q - x;        // patch column for this thread
        if (pq >= 0 && pq < PW) {
            const float* __restrict__ p =
                patches + ((size_t)(n * C + c)) * (PH * PW);
            const int base = TY - y + rg; // patch row for k=0
            #pragma unroll
            for (int k = 0; k < 16; k++) {
                const int pr = base + 4 * k;
                if (pr >= 0 && pr < PH) {
                    acc[k] += p[pr * PW + pq];
                }
            }
        }
    }

    float* __restrict__ ob = out + ((size_t)c * H + TY) * W + TX;
    #pragma unroll
    for (int k = 0; k < 16; k++) {
        ob[(size_t)(rg + 4 * k) * W + q] = acc[k];
    }
}

extern "C" void kernel_launch(void* const* d_in, const int* in_sizes, int n_in,
                              void* d_out, int out_size) {
    const float* patches   = (const float*)d_in[0];
    const int*   positions = (const int*)d_in[1];
    float*       out       = (float*)d_out;

    reset_kernel<<<(NTILES + 255) / 256, 256>>>();
    bin_kernel<<<(N_SRC + 255) / 256, 256>>>(positions);

    dim3 grid(NTILES, C);
    gather_kernel<<<grid, 256>>>(patches, positions, out);
}

// round 9
// speedup vs baseline: 1.0055x; 1.0055x over previous
#include <cuda_runtime.h>
#include <cstdint>

// Scene splatting via tile-binned GATHER:
// out[c, y+r, x+q] += patches[n, c, r, q]; frame C=5,H=4096,W=4096; N=2000 64x64 patches.
// Each 64x64 output tile gathers its overlapping patches and is written exactly once
// (fuses zeroing + accumulation; no atomics on the output).

static constexpr int C  = 5;
static constexpr int H  = 4096;
static constexpr int W  = 4096;
static constexpr int PH = 64;
static constexpr int PW = 64;
static constexpr int N_SRC = 2000;

static constexpr int TILE    = 64;
static constexpr int TILES_X = W / TILE;   // 64
static constexpr int TILES_Y = H / TILE;   // 64
static constexpr int NTILES  = TILES_X * TILES_Y;  // 4096
static constexpr int MAXP    = 128;        // max patches binned per tile (mean ~2)

// Scratch: device globals (no cudaMalloc allowed).
__device__ int g_cnt[NTILES];
__device__ int g_list[NTILES][MAXP];

// ---------------------------------------------------------------------------
// Kernel 0: reset per-tile counters.
// ---------------------------------------------------------------------------
__global__ void reset_kernel() {
    int i = blockIdx.x * blockDim.x + threadIdx.x;
    if (i < NTILES) g_cnt[i] = 0;
}

// ---------------------------------------------------------------------------
// Kernel 1: bin each patch into the (<=4) tiles it overlaps.
// ---------------------------------------------------------------------------
__global__ void bin_kernel(const int* __restrict__ positions) {
    int n = blockIdx.x * blockDim.x + threadIdx.x;
    if (n >= N_SRC) return;
    const int y = positions[2 * n + 0];
    const int x = positions[2 * n + 1];
    const int ty0 = y >> 6, ty1 = (y + PH - 1) >> 6;
    const int tx0 = x >> 6, tx1 = (x + PW - 1) >> 6;
    for (int ty = ty0; ty <= ty1; ty++) {
        for (int tx = tx0; tx <= tx1; tx++) {
            const int t = ty * TILES_X + tx;
            const int slot = atomicAdd(&g_cnt[t], 1);
            if (slot < MAXP) g_list[t][slot] = n;
        }
    }
}

// ---------------------------------------------------------------------------
// Kernel 2: gather. One CTA per (spatial tile, channel).
// 256 threads; thread (q = tid&63, rg = tid>>6) owns pixels (rg+4k, q), k=0..15,
// accumulated in registers. Patch reads and output writes are 128B-coalesced
// per warp. Writes the tile exactly once (zero-filled where no patch covers).
// ---------------------------------------------------------------------------
__global__ __launch_bounds__(256) void gather_kernel(
    const float* __restrict__ patches,    // [N, C, PH, PW]
    const int*   __restrict__ positions,  // [N, 2] (y, x)
    float* __restrict__ out)              // [C, H, W]
{
    const int tile = blockIdx.x;          // 0 .. 4095
    const int c    = blockIdx.y;          // 0 .. 4
    const int TY   = (tile >> 6) * TILE;
    const int TX   = (tile & 63) * TILE;

    const int tid = threadIdx.x;
    const int q   = tid & 63;             // column within tile
    const int rg  = tid >> 6;             // row-group (0..3)

    float acc[16];
    #pragma unroll
    for (int k = 0; k < 16; k++) acc[k] = 0.0f;

    int cnt = g_cnt[tile];
    if (cnt > MAXP) cnt = MAXP;

    for (int i = 0; i < cnt; i++) {
        const int n = g_list[tile][i];
        const int y = positions[2 * n + 0];
        const int x = positions[2 * n + 1];

        const int pq = TX + q - x;        // patch column for this thread
        if (pq >= 0 && pq < PW) {
            const float* __restrict__ p =
                patches + ((size_t)(n * C + c)) * (PH * PW);
            const int base = TY - y + rg; // patch row for k=0
            #pragma unroll
            for (int k = 0; k < 16; k++) {
                const int pr = base + 4 * k;
                if (pr >= 0 && pr < PH) {
                    acc[k] += p[pr * PW + pq];
                }
            }
        }
    }

    float* __restrict__ ob = out + ((size_t)c * H + TY) * W + TX;
    #pragma unroll
    for (int k = 0; k < 16; k++) {
        ob[(size_t)(rg + 4 * k) * W + q] = acc[k];
    }
}

extern "C" void kernel_launch(void* const* d_in, const int* in_sizes, int n_in,
                              void* d_out, int out_size) {
    const float* patches   = (const float*)d_in[0];
    const int*   positions = (const int*)d_in[1];
    float*       out       = (float*)d_out;

    reset_kernel<<<(NTILES + 255) / 256, 256>>>();
    bin_kernel<<<(N_SRC + 255) / 256, 256>>>(positions);

    dim3 grid(NTILES, C);
    gather_kernel<<<grid, 256>>>(patches, positions, out);
}